// round 5
// baseline (speedup 1.0000x reference)
#include <cuda_runtime.h>
#include <cuda_bf16.h>

#define BB      16
#define SS      1024
#define HH      256
#define DMAX    4
#define TOUT    (SS * DMAX)          // 4096
#define NPITCH  256
#define NENERGY 256
#define H4      (HH / 4)             // 64 float4 per row

// frame -> source phoneme index; -1 = padding. 16*4096*4B = 256KB scratch.
__device__ int g_src[BB * TOUT];

// ---------------------------------------------------------------------------
// Kernel 1: per-batch duration round + warp-shuffle scan + scatter src map.
// ---------------------------------------------------------------------------
__global__ void prep_kernel(const float* __restrict__ dur,
                            float* __restrict__ len_tail, int write_len)
{
    __shared__ int wpre[33];            // wpre[w+1] = inclusive sum of warps 0..w
    const int b    = blockIdx.x;
    const int i    = threadIdx.x;
    const int wid  = i >> 5;
    const int lane = i & 31;

    int d = __float2int_rn(dur[b * SS + i]);
    d = max(d, 0);

    // intra-warp inclusive scan
    int x = d;
    #pragma unroll
    for (int off = 1; off < 32; off <<= 1) {
        int v = __shfl_up_sync(0xFFFFFFFFu, x, off);
        if (lane >= off) x += v;
    }
    if (lane == 31) wpre[wid + 1] = x;
    if (i == 0)     wpre[0] = 0;
    __syncthreads();

    if (wid == 0) {
        int v = wpre[lane + 1];
        #pragma unroll
        for (int off = 1; off < 32; off <<= 1) {
            int u = __shfl_up_sync(0xFFFFFFFFu, v, off);
            if (lane >= off) v += u;
        }
        wpre[lane + 1] = v;
    }
    __syncthreads();

    const int csum = x + wpre[wid];     // inclusive prefix over all 1024
    const int len  = wpre[32];

    int* srcb = g_src + b * TOUT;
    for (int t = csum - d; t < csum; ++t)
        srcb[t] = i;

    for (int t = len + i; t < TOUT; t += SS)
        srcb[t] = -1;

    if (write_len && i == 0)
        len_tail[b] = (float)len;
}

// ---------------------------------------------------------------------------
// quantize: replicate searchsorted(linspace(vmin,vmax,nb), v, side='left')
// ---------------------------------------------------------------------------
__device__ __forceinline__ int qbin(float v, float vmin, float vmax, int nb)
{
    v = fminf(fmaxf(v, vmin), vmax);
    const float step = (vmax - vmin) / (float)(nb - 1);
    float u = (v - vmin) / step;
    int i = (int)ceilf(u);
    i = min(max(i, 0), nb - 1);
    while (i > 0 && (vmin + (float)(i - 1) * step) >= v) --i;
    while (i < nb - 1 && (vmin + (float)i * step) < v) ++i;
    return i;
}

__device__ __forceinline__ float4 f4add3m(float4 a, float4 b, float4 c, float m)
{
    float4 r;
    r.x = (a.x + b.x + c.x) * m;
    r.y = (a.y + b.y + c.y) * m;
    r.z = (a.z + b.z + c.z) * m;
    r.w = (a.w + b.w + c.w) * m;
    return r;
}

// ---------------------------------------------------------------------------
// Kernel 2: expand + embed — BRANCH-FREE mainloop.
// One warp handles 2 rows; lane covers float4 columns {lane, lane+32}.
// Pad rows read index 0 of enc/tables (L1-hit, same addr warp-wide) and are
// masked by multiply. All 12 LDG.128 are unconditional and independent, so
// ptxas front-batches them => high MLP per thread.
// ---------------------------------------------------------------------------
__global__ void __launch_bounds__(256)
expand_kernel(const float4* __restrict__ enc,
              const float*  __restrict__ pitch_t,
              const float*  __restrict__ energy_t,
              const float4* __restrict__ ptab,
              const float4* __restrict__ etab,
              float4* __restrict__ out)
{
    const int warp = blockIdx.x * 8 + (threadIdx.x >> 5);
    const int lane = threadIdx.x & 31;
    const int r0   = warp * 2;                  // rows r0, r0+1 (same batch)

    // lanes 0/1 compute packed meta for their row; pad -> all-zero indices
    unsigned meta_l = 0u;
    if (lane < 2) {
        const int row = r0 + lane;
        const int s = g_src[row];
        if (s >= 0) {
            const int pb = qbin(pitch_t[row],  50.0f, 400.0f, NPITCH);
            const int eb = qbin(energy_t[row],  0.0f,   1.0f, NENERGY);
            meta_l = 0x80000000u | ((unsigned)s << 16) | ((unsigned)pb << 8) | (unsigned)eb;
        }
    }
    const unsigned m0 = __shfl_sync(0xFFFFFFFFu, meta_l, 0);
    const unsigned m1 = __shfl_sync(0xFFFFFFFFu, meta_l, 1);

    const int b  = r0 >> 12;                    // TOUT = 4096
    const int j0 = lane;
    const int j1 = lane + 32;

    const float mask0 = (m0 >> 31) ? 1.0f : 0.0f;
    const float mask1 = (m1 >> 31) ? 1.0f : 0.0f;

    const int eoff0 = ((b * SS) + (int)((m0 >> 16) & 1023u)) << 6;
    const int eoff1 = ((b * SS) + (int)((m1 >> 16) & 1023u)) << 6;
    const int poff0 = (int)((m0 >> 8) & 255u) << 6;
    const int poff1 = (int)((m1 >> 8) & 255u) << 6;
    const int qoff0 = (int)(m0 & 255u) << 6;
    const int qoff1 = (int)(m1 & 255u) << 6;

    // 12 independent gathers — no branches between them
    float4 e0a = enc [eoff0 + j0];
    float4 e0b = enc [eoff0 + j1];
    float4 e1a = enc [eoff1 + j0];
    float4 e1b = enc [eoff1 + j1];
    float4 p0a = ptab[poff0 + j0];
    float4 p0b = ptab[poff0 + j1];
    float4 p1a = ptab[poff1 + j0];
    float4 p1b = ptab[poff1 + j1];
    float4 q0a = etab[qoff0 + j0];
    float4 q0b = etab[qoff0 + j1];
    float4 q1a = etab[qoff1 + j0];
    float4 q1b = etab[qoff1 + j1];

    float4 o0a = f4add3m(e0a, p0a, q0a, mask0);
    float4 o0b = f4add3m(e0b, p0b, q0b, mask0);
    float4 o1a = f4add3m(e1a, p1a, q1a, mask1);
    float4 o1b = f4add3m(e1b, p1b, q1b, mask1);

    __stcs(&out[(long)r0 * H4 + j0],       o0a);
    __stcs(&out[(long)r0 * H4 + j1],       o0b);
    __stcs(&out[(long)(r0 + 1) * H4 + j0], o1a);
    __stcs(&out[(long)(r0 + 1) * H4 + j1], o1b);
}

// ---------------------------------------------------------------------------
extern "C" void kernel_launch(void* const* d_in, const int* in_sizes, int n_in,
                              void* d_out, int out_size)
{
    const float* enc      = (const float*)d_in[0];  // [B,S,H]
    const float* pitch_t  = (const float*)d_in[1];  // [B,TOUT]
    const float* energy_t = (const float*)d_in[2];  // [B,TOUT]
    const float* dur      = (const float*)d_in[3];  // [B,S]
    const float* ptab     = (const float*)d_in[4];  // [NPITCH,H]
    const float* etab     = (const float*)d_in[5];  // [NENERGY,H]

    const long long main_elems = (long long)BB * TOUT * HH;
    const int write_len = (out_size > (int)main_elems) ? 1 : 0;
    float* len_tail = (float*)d_out + main_elems;

    prep_kernel<<<BB, SS>>>(dur, len_tail, write_len);

    const int nrows = BB * TOUT;                 // 65536
    // 2 rows/warp, 8 warps/block => 16 rows/block => 4096 blocks
    expand_kernel<<<nrows / 16, 256>>>(
        (const float4*)enc, pitch_t, energy_t,
        (const float4*)ptab, (const float4*)etab,
        (float4*)d_out);
}